// round 12
// baseline (speedup 1.0000x reference)
#include <cuda_runtime.h>
#include <cstdint>

#define Bsz 64
#define Ssz 2048
#define Isz 512
#define Hsz 512

// ============================================================
// Phase 1: xW = x @ W + b   (M=131072, K=512, N=512)
// 128x128 block tile, BK=8, 256 threads, 8x8 thread tile,
// packed f32x2 FMA. 2 CTAs/SM hides sync bubbles.
// ============================================================
__global__ __launch_bounds__(256, 2) void sgemm_xw(
    const float* __restrict__ A,
    const float* __restrict__ Wm,
    const float* __restrict__ bias,
    float* __restrict__ C)
{
    constexpr int K = 512, N = 512;
    __shared__ float As[8][128];
    __shared__ float Bs[8][128];

    const int tid  = threadIdx.x;
    const int bm   = blockIdx.y, bn = blockIdx.x;
    const int arow = tid >> 1, acol = (tid & 1) << 2;
    const int brow = tid >> 5, bcol = (tid & 31) << 2;
    const int tx   = tid & 15, ty = tid >> 4;

    const float* Ab = A + (size_t)bm * 128 * K;
    const float* Bb = Wm + bn * 128;

    unsigned long long acc[8][4];
#pragma unroll
    for (int i = 0; i < 8; i++)
#pragma unroll
        for (int j = 0; j < 4; j++) acc[i][j] = 0ull;

    for (int kk = 0; kk < K; kk += 8) {
        float4 av = *(const float4*)(Ab + (size_t)arow * K + kk + acol);
        float4 bv = *(const float4*)(Bb + (size_t)(kk + brow) * N + bcol);
        __syncthreads();
        As[acol + 0][arow] = av.x;
        As[acol + 1][arow] = av.y;
        As[acol + 2][arow] = av.z;
        As[acol + 3][arow] = av.w;
        *(float4*)&Bs[brow][bcol] = bv;
        __syncthreads();
#pragma unroll
        for (int k = 0; k < 8; k++) {
            float4 a0 = *(const float4*)&As[k][ty * 8];
            float4 a1 = *(const float4*)&As[k][ty * 8 + 4];
            ulonglong2 b0 = *(const ulonglong2*)&Bs[k][tx * 8];
            ulonglong2 b1 = *(const ulonglong2*)&Bs[k][tx * 8 + 4];
            float ar[8] = {a0.x, a0.y, a0.z, a0.w, a1.x, a1.y, a1.z, a1.w};
            unsigned long long br[4] = {b0.x, b0.y, b1.x, b1.y};
#pragma unroll
            for (int i = 0; i < 8; i++) {
                unsigned long long ad;
                unsigned int au = __float_as_uint(ar[i]);
                asm("mov.b64 %0, {%1, %1};" : "=l"(ad) : "r"(au));
#pragma unroll
                for (int j = 0; j < 4; j++)
                    asm("fma.rn.f32x2 %0, %1, %2, %0;"
                        : "+l"(acc[i][j]) : "l"(ad), "l"(br[j]));
            }
        }
    }

    const int cb = bn * 128 + tx * 8;
    ulonglong2 bb0 = *(const ulonglong2*)&bias[cb];
    ulonglong2 bb1 = *(const ulonglong2*)&bias[cb + 4];
    unsigned long long bz[4] = {bb0.x, bb0.y, bb1.x, bb1.y};
#pragma unroll
    for (int i = 0; i < 8; i++) {
        size_t row = (size_t)bm * 128 + ty * 8 + i;
        float* Crow = C + row * N + cb;
#pragma unroll
        for (int j = 0; j < 4; j++) {
            unsigned long long v;
            asm("add.rn.f32x2 %0, %1, %2;" : "=l"(v) : "l"(acc[i][j]), "l"(bz[j]));
            *(unsigned long long*)(Crow + 2 * j) = v;
        }
    }
}

// fast tanh: 1 - 2/(exp(2x)+1) via MUFU EX2 + RCP (abs err ~1e-7).
__device__ __forceinline__ float fast_tanh(float x) {
    float e;
    asm("ex2.approx.f32 %0, %1;" : "=f"(e) : "f"(x * 2.8853900817779268f));
    float r;
    asm("rcp.approx.f32 %0, %1;" : "=f"(r) : "f"(e + 1.0f));
    return fmaf(-2.0f, r, 1.0f);
}

__device__ __forceinline__ void mbar_wait(unsigned int addr, unsigned int parity) {
    unsigned int done;
    do {
        asm volatile(
            "{\n\t.reg .pred p;\n\t"
            "mbarrier.try_wait.parity.acquire.cta.shared::cta.b64 p, [%1], %2, 0x989680;\n\t"
            "selp.b32 %0, 1, 0, p;\n\t}"
            : "=r"(done) : "r"(addr), "r"(parity) : "memory");
    } while (!done);
}

// ============================================================
// Phase 2: persistent cluster RNN scan — cluster 16, U fully
// register-resident, 2 CTAs/SM.
// 16 clusters x 16 CTAs (grid 256, occ 2), 256 threads/CTA,
// 4 batches per cluster. CTA rank r owns columns [32r, 32r+32);
// warp ks (0..7) owns k-range [64ks, 64ks+64): each lane holds
// 32 packed U k-pairs (64 regs) for its single column. NO U in
// smem, NO spills. Warp ks consumes only ranks {2ks,2ks+1}'s
// 512B h-blocks -> 8 per-warp mbarriers; warp starts FMA the
// moment its own inbound blocks land. Exchange: 15 x 512B
// cp.async.bulk, complete_tx on receiver's warp barrier.
// ============================================================
__global__ void __launch_bounds__(256, 2) __cluster_dims__(16, 1, 1)
rnn_scan(const float* __restrict__ U,      // [512,512] row-major [k][h]
         float* __restrict__ hidden,       // [B,S,H]: in = xW+b, out = h
         float* __restrict__ hlast)        // [B,H]
{
    __shared__ __align__(128) float hbuf[2][256][4][2];   // [buf][kp][b][kk] 16KB
    __shared__ __align__(16)  float red[8][32][4];        // [ks][col][b] 4KB
    __shared__ __align__(16)  unsigned long long mbar[8][2]; // [warp-quarter][buf]

    const int tid = threadIdx.x;
    unsigned int rank;
    asm("mov.u32 %0, %%cluster_ctarank;" : "=r"(rank));   // 0..15
    const int cid = blockIdx.x >> 4;       // cluster id 0..15
    const int b0  = cid * 4;               // 4 batches per cluster
    const int ks  = tid >> 5;              // 0..7 (k-split; one warp each)
    const int c   = tid & 31;              // column within CTA's 32
    const int cg  = (int)rank * 32 + c;    // global column 0..511

    // U k-pairs fully in registers: Upack[j] = (U[k0][cg], U[k0+1][cg]),
    // k0 = ks*64 + 2j, j = 0..31.  (64 registers)
    unsigned long long Upack[32];
#pragma unroll
    for (int j = 0; j < 32; j++) {
        int k0 = ks * 64 + 2 * j;
        unsigned int lo = __float_as_uint(U[(size_t)k0 * Hsz + cg]);
        unsigned int hi = __float_as_uint(U[(size_t)(k0 + 1) * Hsz + cg]);
        asm("mov.b64 %0, {%1, %2};" : "=l"(Upack[j]) : "r"(lo), "r"(hi));
    }

    const unsigned int hb_base =
        (unsigned int)__cvta_generic_to_shared(&hbuf[0][0][0][0]);
    const unsigned int mb_base =
        (unsigned int)__cvta_generic_to_shared(&mbar[0][0]);

    // Warp ks receives from ranks {2ks, 2ks+1} (512B each); if this CTA's
    // own rank is one of them, that block is written locally (no tx).
    const unsigned int expq =
        ((int)(rank >> 1) == ks) ? 512u : 1024u;
    const unsigned int my_mb = mb_base + (unsigned int)ks * 16u;

    // Init: zero both h buffers; 16 mbarriers count=1; pre-arm buffer-1 set.
    {
        float* hz = &hbuf[0][0][0][0];
        for (int i = tid; i < 2 * 256 * 4 * 2; i += 256) hz[i] = 0.0f;
    }
    if (tid == 0) {
#pragma unroll
        for (int qq = 0; qq < 8; qq++) {
#pragma unroll
            for (int b = 0; b < 2; b++)
                asm volatile("mbarrier.init.shared.b64 [%0], %1;"
                             :: "r"(mb_base + qq * 16u + b * 8u), "r"(1u)
                             : "memory");
            const unsigned int e =
                ((int)(rank >> 1) == qq) ? 512u : 1024u;
            asm volatile("mbarrier.arrive.expect_tx.shared.b64 _, [%0], %1;"
                         :: "r"(mb_base + qq * 16u + 8u), "r"(e) : "memory");
        }
    }
    __syncthreads();
    asm volatile("barrier.cluster.arrive.aligned;" ::: "memory");
    asm volatile("barrier.cluster.wait.aligned;" ::: "memory");

    // Epilogue mapping (tid < 128): one (column, batch) value per thread.
    const int ec  = tid & 31;
    const int eb  = (tid >> 5) & 3;
    const int egc = (int)rank * 32 + ec;
    size_t gaddr = 0;
    if (tid < 128)
        gaddr = ((size_t)(b0 + eb) * Ssz) * Hsz + egc;

    unsigned int ph0 = 0, ph1 = 0;

    for (int t = 0; t < Ssz; t++) {
        const int q = t & 1;
        const unsigned int mbq = my_mb + (unsigned int)q * 8u;

        // xw prefetch (independent of the wait; issue early).
        float xw = 0.0f;
        if (tid < 128)
            xw = __ldg(hidden + gaddr);

        // Wait only for OUR warp's inbound blocks (buffer q).
        if (t > 0) {
            if (q == 0) { mbar_wait(mbq, ph0); ph0 ^= 1; }
            else        { mbar_wait(mbq, ph1); ph1 ^= 1; }
        }
        // Re-arm our warp barrier for its next phase (consumed at t+2).
        if ((tid & 31) == 0)
            asm volatile("mbarrier.arrive.expect_tx.shared.b64 _, [%0], %1;"
                         :: "r"(mbq), "r"(expq) : "memory");

        // ---- partials: 4 batches x 1 col x 32 k-pairs (f32x2) ----
        // quarter ks covers kp [32ks, 32ks+32); 32B per kp (4 batches).
        const ulonglong2* hk =
            (const ulonglong2*)((char*)hbuf + q * 8192 + ks * 1024);
        unsigned long long a0 = 0ull, a1 = 0ull, a2 = 0ull, a3 = 0ull;
#pragma unroll
        for (int j = 0; j < 32; j++) {
            ulonglong2 p01 = hk[2 * j];       // (b0 pair, b1 pair)
            ulonglong2 p23 = hk[2 * j + 1];   // (b2 pair, b3 pair)
            asm("fma.rn.f32x2 %0, %1, %2, %0;" : "+l"(a0) : "l"(Upack[j]), "l"(p01.x));
            asm("fma.rn.f32x2 %0, %1, %2, %0;" : "+l"(a1) : "l"(Upack[j]), "l"(p01.y));
            asm("fma.rn.f32x2 %0, %1, %2, %0;" : "+l"(a2) : "l"(Upack[j]), "l"(p23.x));
            asm("fma.rn.f32x2 %0, %1, %2, %0;" : "+l"(a3) : "l"(Upack[j]), "l"(p23.y));
        }
        float s0, s1, s2, s3;
        {
            unsigned int l, h;
            asm("mov.b64 {%0, %1}, %2;" : "=r"(l), "=r"(h) : "l"(a0));
            s0 = __uint_as_float(l) + __uint_as_float(h);
            asm("mov.b64 {%0, %1}, %2;" : "=r"(l), "=r"(h) : "l"(a1));
            s1 = __uint_as_float(l) + __uint_as_float(h);
            asm("mov.b64 {%0, %1}, %2;" : "=r"(l), "=r"(h) : "l"(a2));
            s2 = __uint_as_float(l) + __uint_as_float(h);
            asm("mov.b64 {%0, %1}, %2;" : "=r"(l), "=r"(h) : "l"(a3));
            s3 = __uint_as_float(l) + __uint_as_float(h);
        }
        *(float4*)&red[ks][c][0] = make_float4(s0, s1, s2, s3);
        __syncthreads();

        // ---- epilogue (tid < 128): one value each ----
        if (tid < 128) {
            float v = xw +
                (((red[0][ec][eb] + red[1][ec][eb]) +
                  (red[2][ec][eb] + red[3][ec][eb])) +
                 ((red[4][ec][eb] + red[5][ec][eb]) +
                  (red[6][ec][eb] + red[7][ec][eb])));
            v = fast_tanh(v);

            // local write into hbuf[q^1], k-pair layout
            hbuf[q ^ 1][egc >> 1][eb][egc & 1] = v;

            hidden[gaddr] = v;               // overwrite xw[t] in place
            if (t == Ssz - 1)
                hlast[(size_t)(b0 + eb) * Hsz + egc] = v;
            else
                gaddr += Hsz;
        }
        __syncthreads();   // own block fully written before bulk reads it

        // ---- push own 512B block to the 15 peers' hbuf[q^1], targeting
        // the receiver-side warp barrier for OUR rank's k-range ----
        if (tid < 15) {
            asm volatile("fence.proxy.async.shared::cta;" ::: "memory");
            const unsigned int off =
                (unsigned int)(q ^ 1) * 8192u + rank * 512u;
            const unsigned int src = hb_base + off;
            const unsigned int pr  = (rank + 1u + (unsigned int)tid) & 15u;
            const unsigned int mb_tgt =
                mb_base + (rank >> 1) * 16u + (unsigned int)(q ^ 1) * 8u;
            unsigned int dst, rmb;
            asm("mapa.shared::cluster.u32 %0, %1, %2;"
                : "=r"(dst) : "r"(src), "r"(pr));
            asm("mapa.shared::cluster.u32 %0, %1, %2;"
                : "=r"(rmb) : "r"(mb_tgt), "r"(pr));
            asm volatile(
                "cp.async.bulk.shared::cluster.shared::cta.mbarrier::complete_tx::bytes "
                "[%0], [%1], %2, [%3];"
                :: "r"(dst), "r"(src), "r"(512u), "r"(rmb) : "memory");
        }
    }

    // Drain the final inbound phase (t=2047 targets buffer-0 barriers):
    // each warp waits its own barrier, then cluster-sync before exit.
    mbar_wait(my_mb, ph0);
    asm volatile("barrier.cluster.arrive.aligned;" ::: "memory");
    asm volatile("barrier.cluster.wait.aligned;" ::: "memory");
}

extern "C" void kernel_launch(void* const* d_in, const int* in_sizes, int n_in,
                              void* d_out, int out_size) {
    const float* x  = (const float*)d_in[0];   // [64,2048,512]
    const float* Wi = (const float*)d_in[1];   // [512,512]
    const float* Ui = (const float*)d_in[2];   // [512,512]
    const float* bi = (const float*)d_in[3];   // [512]

    float* hidden = (float*)d_out;                        // [B,S,H]
    float* hlast  = hidden + (size_t)Bsz * Ssz * Hsz;     // [B,H]

    dim3 g1(Hsz / 128, (Bsz * Ssz) / 128);   // (4, 1024)
    sgemm_xw<<<g1, 256>>>(x, Wi, bi, hidden);

    // Phase 2: 16 clusters x 16 CTAs (non-portable cluster size),
    // 2 CTAs/SM, U fully register-resident.
    static int attr_set = 0;
    if (!attr_set) {
        cudaFuncSetAttribute(rnn_scan,
                             cudaFuncAttributeNonPortableClusterSizeAllowed, 1);
        attr_set = 1;
    }
    rnn_scan<<<256, 256>>>(Ui, hidden, hlast);
}

// round 13
// speedup vs baseline: 1.2607x; 1.2607x over previous
#include <cuda_runtime.h>
#include <cstdint>

#define Bsz 64
#define Ssz 2048
#define Isz 512
#define Hsz 512

// ============================================================
// Phase 1: xW = x @ W + b   (M=131072, K=512, N=512)
// 128x128 block tile, BK=8, 256 threads, 8x8 thread tile,
// packed f32x2 FMA. 2 CTAs/SM hides sync bubbles.
// ============================================================
__global__ __launch_bounds__(256, 2) void sgemm_xw(
    const float* __restrict__ A,
    const float* __restrict__ Wm,
    const float* __restrict__ bias,
    float* __restrict__ C)
{
    constexpr int K = 512, N = 512;
    __shared__ float As[8][128];
    __shared__ float Bs[8][128];

    const int tid  = threadIdx.x;
    const int bm   = blockIdx.y, bn = blockIdx.x;
    const int arow = tid >> 1, acol = (tid & 1) << 2;
    const int brow = tid >> 5, bcol = (tid & 31) << 2;
    const int tx   = tid & 15, ty = tid >> 4;

    const float* Ab = A + (size_t)bm * 128 * K;
    const float* Bb = Wm + bn * 128;

    unsigned long long acc[8][4];
#pragma unroll
    for (int i = 0; i < 8; i++)
#pragma unroll
        for (int j = 0; j < 4; j++) acc[i][j] = 0ull;

    for (int kk = 0; kk < K; kk += 8) {
        float4 av = *(const float4*)(Ab + (size_t)arow * K + kk + acol);
        float4 bv = *(const float4*)(Bb + (size_t)(kk + brow) * N + bcol);
        __syncthreads();
        As[acol + 0][arow] = av.x;
        As[acol + 1][arow] = av.y;
        As[acol + 2][arow] = av.z;
        As[acol + 3][arow] = av.w;
        *(float4*)&Bs[brow][bcol] = bv;
        __syncthreads();
#pragma unroll
        for (int k = 0; k < 8; k++) {
            float4 a0 = *(const float4*)&As[k][ty * 8];
            float4 a1 = *(const float4*)&As[k][ty * 8 + 4];
            ulonglong2 b0 = *(const ulonglong2*)&Bs[k][tx * 8];
            ulonglong2 b1 = *(const ulonglong2*)&Bs[k][tx * 8 + 4];
            float ar[8] = {a0.x, a0.y, a0.z, a0.w, a1.x, a1.y, a1.z, a1.w};
            unsigned long long br[4] = {b0.x, b0.y, b1.x, b1.y};
#pragma unroll
            for (int i = 0; i < 8; i++) {
                unsigned long long ad;
                unsigned int au = __float_as_uint(ar[i]);
                asm("mov.b64 %0, {%1, %1};" : "=l"(ad) : "r"(au));
#pragma unroll
                for (int j = 0; j < 4; j++)
                    asm("fma.rn.f32x2 %0, %1, %2, %0;"
                        : "+l"(acc[i][j]) : "l"(ad), "l"(br[j]));
            }
        }
    }

    const int cb = bn * 128 + tx * 8;
    ulonglong2 bb0 = *(const ulonglong2*)&bias[cb];
    ulonglong2 bb1 = *(const ulonglong2*)&bias[cb + 4];
    unsigned long long bz[4] = {bb0.x, bb0.y, bb1.x, bb1.y};
#pragma unroll
    for (int i = 0; i < 8; i++) {
        size_t row = (size_t)bm * 128 + ty * 8 + i;
        float* Crow = C + row * N + cb;
#pragma unroll
        for (int j = 0; j < 4; j++) {
            unsigned long long v;
            asm("add.rn.f32x2 %0, %1, %2;" : "=l"(v) : "l"(acc[i][j]), "l"(bz[j]));
            *(unsigned long long*)(Crow + 2 * j) = v;
        }
    }
}

// fast tanh: 1 - 2/(exp(2x)+1) via MUFU EX2 + RCP (abs err ~1e-7).
__device__ __forceinline__ float fast_tanh(float x) {
    float e;
    asm("ex2.approx.f32 %0, %1;" : "=f"(e) : "f"(x * 2.8853900817779268f));
    float r;
    asm("rcp.approx.f32 %0, %1;" : "=f"(r) : "f"(e + 1.0f));
    return fmaf(-2.0f, r, 1.0f);
}

__device__ __forceinline__ void mbar_wait(unsigned int addr, unsigned int parity) {
    unsigned int done;
    do {
        asm volatile(
            "{\n\t.reg .pred p;\n\t"
            "mbarrier.try_wait.parity.acquire.cta.shared::cta.b64 p, [%1], %2, 0x989680;\n\t"
            "selp.b32 %0, 1, 0, p;\n\t}"
            : "=r"(done) : "r"(addr), "r"(parity) : "memory");
    } while (!done);
}

// Dynamic smem layout (bytes):
//   [0, 8192)        hbuf[2][256][2][2] floats
//   [8192, 9216)     stage[2][512B]  (outgoing h block, double buffered)
//   [9216, 13312)    red[2][4][64][2] floats (double buffered by parity)
//   [13312, 13376)   mbar[4][2] u64
//   [13376, 78912)   Usm[32][256] u64  (k-pairs 32..63 of each thread)
#define HB_OFF   0u
#define STG_OFF  8192u
#define RED_OFF  9216u
#define MB_OFF   13312u
#define USM_OFF  13376u
#define SMEM_TOTAL 78912

// ============================================================
// Phase 2: persistent cluster RNN scan — decoupled warp roles.
// 32 clusters x 8 CTAs (grid 256, occ 2), 256 threads/CTA,
// 2 batches per cluster. U: 32 k-pairs in regs + 32 in smem.
// Exchange: epilogue writes stage, 8 x 512B bulk copies (self
// included) deliver to every rank's hbuf with complete_tx on the
// receiver's per-quarter barrier (expect 1024B). Producer warps
// (tid>=128) never block on the epilogue: bar.arrive(2) then race
// to their next quarter wait. red double-buffered; bar 3 protects
// its reuse one step behind the epilogue's reads.
// ============================================================
__global__ void __launch_bounds__(256, 2) __cluster_dims__(8, 1, 1)
rnn_scan(const float* __restrict__ U,      // [512,512] row-major [k][h]
         float* __restrict__ hidden,       // [B,S,H]: in = xW+b, out = h
         float* __restrict__ hlast)        // [B,H]
{
    extern __shared__ __align__(128) char dsm[];

    const int tid = threadIdx.x;
    unsigned int rank;
    asm("mov.u32 %0, %%cluster_ctarank;" : "=r"(rank));
    const int cid = blockIdx.x >> 3;       // cluster id 0..31
    const int b0  = cid * 2;               // 2 batches per cluster
    const int ks  = tid >> 6;              // 0..3 (k-quarter)
    const int c   = tid & 63;
    const int cg  = (int)rank * 64 + c;

    unsigned long long* Usm = (unsigned long long*)(dsm + USM_OFF);

    // U k-pairs for this thread's quarter: j=0..31 in regs, 32..63 in smem.
    unsigned long long Upack[32];
#pragma unroll
    for (int j = 0; j < 32; j++) {
        int k0 = ks * 128 + 2 * j;
        unsigned int lo = __float_as_uint(U[(size_t)k0 * Hsz + cg]);
        unsigned int hi = __float_as_uint(U[(size_t)(k0 + 1) * Hsz + cg]);
        asm("mov.b64 %0, {%1, %2};" : "=l"(Upack[j]) : "r"(lo), "r"(hi));
    }
    for (int j = 32; j < 64; j++) {
        int k0 = ks * 128 + 2 * j;
        unsigned int lo = __float_as_uint(U[(size_t)k0 * Hsz + cg]);
        unsigned int hi = __float_as_uint(U[(size_t)(k0 + 1) * Hsz + cg]);
        unsigned long long u;
        asm("mov.b64 %0, {%1, %2};" : "=l"(u) : "r"(lo), "r"(hi));
        Usm[(j - 32) * 256 + tid] = u;
    }

    const unsigned int hb_base =
        (unsigned int)__cvta_generic_to_shared(dsm + HB_OFF);
    const unsigned int stg_base =
        (unsigned int)__cvta_generic_to_shared(dsm + STG_OFF);
    const unsigned int mb_base =
        (unsigned int)__cvta_generic_to_shared(dsm + MB_OFF);
    float* redp = (float*)(dsm + RED_OFF);

    // Quarter ks receives ranks {2ks,2ks+1}'s 512B blocks — ALL via bulk
    // (self included) -> expect 1024B always.
    const unsigned int my_mb = mb_base + (unsigned int)ks * 16u;

    // Init: zero both h buffers; 8 mbarriers count=1; pre-arm buffer-1 set.
    {
        float* hz = (float*)(dsm + HB_OFF);
        for (int i = tid; i < 2048; i += 256) hz[i] = 0.0f;
    }
    if (tid == 0) {
#pragma unroll
        for (int qq = 0; qq < 4; qq++) {
#pragma unroll
            for (int b = 0; b < 2; b++)
                asm volatile("mbarrier.init.shared.b64 [%0], %1;"
                             :: "r"(mb_base + qq * 16u + b * 8u), "r"(1u)
                             : "memory");
            asm volatile("mbarrier.arrive.expect_tx.shared.b64 _, [%0], %1;"
                         :: "r"(mb_base + qq * 16u + 8u), "r"(1024u) : "memory");
        }
    }
    __syncthreads();
    asm volatile("barrier.cluster.arrive.aligned;" ::: "memory");
    asm volatile("barrier.cluster.wait.aligned;" ::: "memory");

    // Epilogue mapping (tid < 128): one (column, batch) value per thread.
    const int ec  = tid & 63;
    const int eb  = (tid >> 6) & 1;
    const int egc = (int)rank * 64 + ec;
    size_t gaddr = 0;
    if (tid < 128)
        gaddr = ((size_t)(b0 + eb) * Ssz) * Hsz + egc;

    unsigned int ph0 = 0, ph1 = 0;

    for (int t = 0; t < Ssz; t++) {
        const int q = t & 1;
        const unsigned int mbq = my_mb + (unsigned int)q * 8u;

        // xw prefetch (independent of the wait; issue early).
        float xw = 0.0f;
        if (tid < 128)
            xw = __ldg(hidden + gaddr);

        // Wait only for OUR quarter's inbound blocks (buffer q).
        if (t > 0) {
            if (q == 0) { mbar_wait(mbq, ph0); ph0 ^= 1; }
            else        { mbar_wait(mbq, ph1); ph1 ^= 1; }
        }
        // Re-arm our quarter barrier for its next phase (consumed at t+2).
        if ((tid & 63) == 0)
            asm volatile("mbarrier.arrive.expect_tx.shared.b64 _, [%0], %1;"
                         :: "r"(mbq), "r"(1024u) : "memory");

        // ---- partials: 2 batches x 1 col x 64 k-pairs (f32x2) ----
        const ulonglong2* hk =
            (const ulonglong2*)(dsm + HB_OFF + q * 4096 + ks * 1024);
        unsigned long long a0 = 0ull, a1 = 0ull;
#pragma unroll
        for (int j = 0; j < 32; j++) {
            ulonglong2 p = hk[j];             // .x = batch0 k-pair, .y = batch1
            asm("fma.rn.f32x2 %0, %1, %2, %0;" : "+l"(a0) : "l"(Upack[j]), "l"(p.x));
            asm("fma.rn.f32x2 %0, %1, %2, %0;" : "+l"(a1) : "l"(Upack[j]), "l"(p.y));
        }
#pragma unroll
        for (int j = 32; j < 64; j++) {
            unsigned long long u = Usm[(j - 32) * 256 + tid];
            ulonglong2 p = hk[j];
            asm("fma.rn.f32x2 %0, %1, %2, %0;" : "+l"(a0) : "l"(u), "l"(p.x));
            asm("fma.rn.f32x2 %0, %1, %2, %0;" : "+l"(a1) : "l"(u), "l"(p.y));
        }
        float s0, s1;
        {
            unsigned int l, h;
            asm("mov.b64 {%0, %1}, %2;" : "=r"(l), "=r"(h) : "l"(a0));
            s0 = __uint_as_float(l) + __uint_as_float(h);
            asm("mov.b64 {%0, %1}, %2;" : "=r"(l), "=r"(h) : "l"(a1));
            s1 = __uint_as_float(l) + __uint_as_float(h);
        }

        if (tid >= 128) {
            // Producers: protect red[q] reuse (epilogue read it at t-2;
            // arrive(3) at t-1 proves the read finished). Off critical path.
            if (t > 0)
                asm volatile("bar.sync 3, 256;" ::: "memory");
            *(float2*)(redp + ((q * 4 + ks) * 64 + c) * 2) =
                make_float2(s0, s1);
            // Release the epilogue; race ahead to the next wait.
            asm volatile("bar.arrive 2, 256;" ::: "memory");
        } else {
            *(float2*)(redp + ((q * 4 + ks) * 64 + c) * 2) =
                make_float2(s0, s1);
            // Wait for producers' red writes.
            asm volatile("bar.sync 2, 256;" ::: "memory");

            float v = xw + ((redp[((q * 4 + 0) * 64 + ec) * 2 + eb] +
                             redp[((q * 4 + 1) * 64 + ec) * 2 + eb]) +
                            (redp[((q * 4 + 2) * 64 + ec) * 2 + eb] +
                             redp[((q * 4 + 3) * 64 + ec) * 2 + eb]));
            v = fast_tanh(v);
            // Signal red[q] reads done (consumed by producers at t+1).
            asm volatile("bar.arrive 3, 256;" ::: "memory");

            // Write outgoing block into stage[q^1] (block-local layout).
            *(float*)(dsm + STG_OFF + (q ^ 1) * 512 +
                      (ec >> 1) * 16 + eb * 8 + (ec & 1) * 4) = v;

            hidden[gaddr] = v;               // overwrite xw[t] in place
            if (t == Ssz - 1)
                hlast[(size_t)(b0 + eb) * Hsz + egc] = v;
            else
                gaddr += Hsz;

            // Epilogue-only barrier: stage fully written before bulk reads.
            asm volatile("bar.sync 1, 128;" ::: "memory");

            // Push stage to ALL 8 ranks' hbuf[q^1] (self included),
            // complete_tx on the receiver's quarter barrier for our k-range.
            if (tid < 8) {
                asm volatile("fence.proxy.async.shared::cta;" ::: "memory");
                const unsigned int src = stg_base + (unsigned int)(q ^ 1) * 512u;
                const unsigned int pr  = (rank + (unsigned int)tid) & 7u;
                const unsigned int dst_l =
                    hb_base + (unsigned int)(q ^ 1) * 4096u + rank * 512u;
                const unsigned int mb_tgt =
                    mb_base + (rank >> 1) * 16u + (unsigned int)(q ^ 1) * 8u;
                unsigned int dst, rmb;
                asm("mapa.shared::cluster.u32 %0, %1, %2;"
                    : "=r"(dst) : "r"(dst_l), "r"(pr));
                asm("mapa.shared::cluster.u32 %0, %1, %2;"
                    : "=r"(rmb) : "r"(mb_tgt), "r"(pr));
                asm volatile(
                    "cp.async.bulk.shared::cluster.shared::cta.mbarrier::complete_tx::bytes "
                    "[%0], [%1], %2, [%3];"
                    :: "r"(dst), "r"(src), "r"(512u), "r"(rmb) : "memory");
            }
        }
    }

    // Drain the final inbound phase, then cluster-sync before exit.
    mbar_wait(my_mb, ph0);
    asm volatile("barrier.cluster.arrive.aligned;" ::: "memory");
    asm volatile("barrier.cluster.wait.aligned;" ::: "memory");
}

extern "C" void kernel_launch(void* const* d_in, const int* in_sizes, int n_in,
                              void* d_out, int out_size) {
    const float* x  = (const float*)d_in[0];   // [64,2048,512]
    const float* Wi = (const float*)d_in[1];   // [512,512]
    const float* Ui = (const float*)d_in[2];   // [512,512]
    const float* bi = (const float*)d_in[3];   // [512]

    float* hidden = (float*)d_out;                        // [B,S,H]
    float* hlast  = hidden + (size_t)Bsz * Ssz * Hsz;     // [B,H]

    dim3 g1(Hsz / 128, (Bsz * Ssz) / 128);   // (4, 1024)
    sgemm_xw<<<g1, 256>>>(x, Wi, bi, hidden);

    // Phase 2: 32 clusters x 8 CTAs, 2 CTAs/SM, 77 KB dyn smem each.
    cudaFuncSetAttribute(rnn_scan,
                         cudaFuncAttributeMaxDynamicSharedMemorySize,
                         SMEM_TOTAL);
    rnn_scan<<<256, 256, SMEM_TOTAL>>>(Ui, hidden, hlast);
}

// round 14
// speedup vs baseline: 1.5426x; 1.2236x over previous
#include <cuda_runtime.h>
#include <cstdint>

#define Bsz 64
#define Ssz 2048
#define Isz 512
#define Hsz 512

// ============================================================
// Phase 1: xW = x @ W + b   (M=131072, K=512, N=512)
// 128x128 block tile, BK=8, 256 threads, 8x8 thread tile,
// packed f32x2 FMA. 2 CTAs/SM hides sync bubbles.
// ============================================================
__global__ __launch_bounds__(256, 2) void sgemm_xw(
    const float* __restrict__ A,
    const float* __restrict__ Wm,
    const float* __restrict__ bias,
    float* __restrict__ C)
{
    constexpr int K = 512, N = 512;
    __shared__ float As[8][128];
    __shared__ float Bs[8][128];

    const int tid  = threadIdx.x;
    const int bm   = blockIdx.y, bn = blockIdx.x;
    const int arow = tid >> 1, acol = (tid & 1) << 2;
    const int brow = tid >> 5, bcol = (tid & 31) << 2;
    const int tx   = tid & 15, ty = tid >> 4;

    const float* Ab = A + (size_t)bm * 128 * K;
    const float* Bb = Wm + bn * 128;

    unsigned long long acc[8][4];
#pragma unroll
    for (int i = 0; i < 8; i++)
#pragma unroll
        for (int j = 0; j < 4; j++) acc[i][j] = 0ull;

    for (int kk = 0; kk < K; kk += 8) {
        float4 av = *(const float4*)(Ab + (size_t)arow * K + kk + acol);
        float4 bv = *(const float4*)(Bb + (size_t)(kk + brow) * N + bcol);
        __syncthreads();
        As[acol + 0][arow] = av.x;
        As[acol + 1][arow] = av.y;
        As[acol + 2][arow] = av.z;
        As[acol + 3][arow] = av.w;
        *(float4*)&Bs[brow][bcol] = bv;
        __syncthreads();
#pragma unroll
        for (int k = 0; k < 8; k++) {
            float4 a0 = *(const float4*)&As[k][ty * 8];
            float4 a1 = *(const float4*)&As[k][ty * 8 + 4];
            ulonglong2 b0 = *(const ulonglong2*)&Bs[k][tx * 8];
            ulonglong2 b1 = *(const ulonglong2*)&Bs[k][tx * 8 + 4];
            float ar[8] = {a0.x, a0.y, a0.z, a0.w, a1.x, a1.y, a1.z, a1.w};
            unsigned long long br[4] = {b0.x, b0.y, b1.x, b1.y};
#pragma unroll
            for (int i = 0; i < 8; i++) {
                unsigned long long ad;
                unsigned int au = __float_as_uint(ar[i]);
                asm("mov.b64 %0, {%1, %1};" : "=l"(ad) : "r"(au));
#pragma unroll
                for (int j = 0; j < 4; j++)
                    asm("fma.rn.f32x2 %0, %1, %2, %0;"
                        : "+l"(acc[i][j]) : "l"(ad), "l"(br[j]));
            }
        }
    }

    const int cb = bn * 128 + tx * 8;
    ulonglong2 bb0 = *(const ulonglong2*)&bias[cb];
    ulonglong2 bb1 = *(const ulonglong2*)&bias[cb + 4];
    unsigned long long bz[4] = {bb0.x, bb0.y, bb1.x, bb1.y};
#pragma unroll
    for (int i = 0; i < 8; i++) {
        size_t row = (size_t)bm * 128 + ty * 8 + i;
        float* Crow = C + row * N + cb;
#pragma unroll
        for (int j = 0; j < 4; j++) {
            unsigned long long v;
            asm("add.rn.f32x2 %0, %1, %2;" : "=l"(v) : "l"(acc[i][j]), "l"(bz[j]));
            *(unsigned long long*)(Crow + 2 * j) = v;
        }
    }
}

// fast tanh: 1 - 2/(exp(2x)+1) via MUFU EX2 + RCP (abs err ~1e-7).
__device__ __forceinline__ float fast_tanh(float x) {
    float e;
    asm("ex2.approx.f32 %0, %1;" : "=f"(e) : "f"(x * 2.8853900817779268f));
    float r;
    asm("rcp.approx.f32 %0, %1;" : "=f"(r) : "f"(e + 1.0f));
    return fmaf(-2.0f, r, 1.0f);
}

__device__ __forceinline__ void mbar_wait(unsigned int addr, unsigned int parity) {
    unsigned int done;
    do {
        asm volatile(
            "{\n\t.reg .pred p;\n\t"
            "mbarrier.try_wait.parity.acquire.cta.shared::cta.b64 p, [%1], %2, 0x989680;\n\t"
            "selp.b32 %0, 1, 0, p;\n\t}"
            : "=r"(done) : "r"(addr), "r"(parity) : "memory");
    } while (!done);
}

// Dynamic smem layout (bytes):
//   [0, 8192)        hbuf[2][256][2][2] floats
//   [8192, 9216)     stage[2][512B]  (outgoing h block, double buffered)
//   [9216, 17408)    red[2][4][8][32] floats (parity, component, warp, lane)
//   [17408, 17536)   mbar[8][2] u64  (per-warp k-split barriers)
//   [17536, 83072)   Usm[32][256] u64  (col-B U k-pairs per thread)
#define HB_OFF   0u
#define STG_OFF  8192u
#define RED_OFF  9216u
#define MB_OFF   17408u
#define USM_OFF  17536u
#define SMEM_TOTAL 83072

// ============================================================
// Phase 2: persistent cluster RNN scan — per-warp k-split,
// no duplicate h loads.
// 32 clusters x 8 CTAs (grid 256, occ 2), 256 threads/CTA,
// 2 batches per cluster. Warp w owns k-range [64w, 64w+64) and
// ALL 64 CTA columns: lane l computes col A = l (U in 64 regs)
// and col B = l+32 (U from smem). Each 16B h broadcast feeds 4
// FFMA2 (was 2). Warp w consumes exactly rank w's 512B block ->
// per-warp mbarrier with a single sender (expect 512B).
// Exchange: stage + 8 x 512B bulk copies (self included).
// Producer warps 4-7 never block on the epilogue (bar 2/3).
// ============================================================
__global__ void __launch_bounds__(256, 2) __cluster_dims__(8, 1, 1)
rnn_scan(const float* __restrict__ U,      // [512,512] row-major [k][h]
         float* __restrict__ hidden,       // [B,S,H]: in = xW+b, out = h
         float* __restrict__ hlast)        // [B,H]
{
    extern __shared__ __align__(128) char dsm[];

    const int tid  = threadIdx.x;
    unsigned int rank;
    asm("mov.u32 %0, %%cluster_ctarank;" : "=r"(rank));
    const int cid  = blockIdx.x >> 3;      // cluster id 0..31
    const int b0   = cid * 2;              // 2 batches per cluster
    const int w    = tid >> 5;             // warp id = k-split 0..7
    const int lane = tid & 31;
    const int gc0  = (int)rank * 64 + lane;        // column A (regs)
    const int gc1  = gc0 + 32;                     // column B (smem)

    unsigned long long* Usm = (unsigned long long*)(dsm + USM_OFF);

    // U k-pairs for warp w's k-range [64w, 64w+64): col A in registers,
    // col B in shared memory (lane-distinct layout [j][tid]).
    unsigned long long UA[32];
#pragma unroll
    for (int j = 0; j < 32; j++) {
        int k0 = w * 64 + 2 * j;
        unsigned int lo = __float_as_uint(U[(size_t)k0 * Hsz + gc0]);
        unsigned int hi = __float_as_uint(U[(size_t)(k0 + 1) * Hsz + gc0]);
        asm("mov.b64 %0, {%1, %2};" : "=l"(UA[j]) : "r"(lo), "r"(hi));
    }
    for (int j = 0; j < 32; j++) {
        int k0 = w * 64 + 2 * j;
        unsigned int lo = __float_as_uint(U[(size_t)k0 * Hsz + gc1]);
        unsigned int hi = __float_as_uint(U[(size_t)(k0 + 1) * Hsz + gc1]);
        unsigned long long u;
        asm("mov.b64 %0, {%1, %2};" : "=l"(u) : "r"(lo), "r"(hi));
        Usm[j * 256 + tid] = u;
    }

    const unsigned int hb_base =
        (unsigned int)__cvta_generic_to_shared(dsm + HB_OFF);
    const unsigned int stg_base =
        (unsigned int)__cvta_generic_to_shared(dsm + STG_OFF);
    const unsigned int mb_base =
        (unsigned int)__cvta_generic_to_shared(dsm + MB_OFF);
    float* redp = (float*)(dsm + RED_OFF);

    // Warp w consumes exactly rank w's 512B block (self included via bulk).
    const unsigned int my_mb = mb_base + (unsigned int)w * 16u;

    // Init: zero both h buffers; 16 mbarriers count=1; pre-arm buffer-1 set.
    {
        float* hz = (float*)(dsm + HB_OFF);
        for (int i = tid; i < 2048; i += 256) hz[i] = 0.0f;
    }
    if (tid == 0) {
#pragma unroll
        for (int qq = 0; qq < 8; qq++) {
#pragma unroll
            for (int b = 0; b < 2; b++)
                asm volatile("mbarrier.init.shared.b64 [%0], %1;"
                             :: "r"(mb_base + qq * 16u + b * 8u), "r"(1u)
                             : "memory");
            asm volatile("mbarrier.arrive.expect_tx.shared.b64 _, [%0], %1;"
                         :: "r"(mb_base + qq * 16u + 8u), "r"(512u) : "memory");
        }
    }
    __syncthreads();
    asm volatile("barrier.cluster.arrive.aligned;" ::: "memory");
    asm volatile("barrier.cluster.wait.aligned;" ::: "memory");

    // Epilogue mapping (tid < 128): one (column, batch) value per thread.
    const int ec  = tid & 63;
    const int eb  = (tid >> 6) & 1;
    const int egc = (int)rank * 64 + ec;
    // red component for this (col, batch): colhalf*2 + batch.
    const int ecomp = (ec >> 5) * 2 + eb;
    const int elane = ec & 31;
    size_t gaddr = 0;
    if (tid < 128)
        gaddr = ((size_t)(b0 + eb) * Ssz) * Hsz + egc;

    unsigned int ph0 = 0, ph1 = 0;

    for (int t = 0; t < Ssz; t++) {
        const int q = t & 1;
        const unsigned int mbq = my_mb + (unsigned int)q * 8u;

        // xw prefetch (independent of the wait; issue early).
        float xw = 0.0f;
        if (tid < 128)
            xw = __ldg(hidden + gaddr);

        // Wait for OUR warp's single inbound block (buffer q).
        if (t > 0) {
            if (q == 0) { mbar_wait(mbq, ph0); ph0 ^= 1; }
            else        { mbar_wait(mbq, ph1); ph1 ^= 1; }
        }
        // Re-arm our warp barrier for its next phase (consumed at t+2).
        if (lane == 0)
            asm volatile("mbarrier.arrive.expect_tx.shared.b64 _, [%0], %1;"
                         :: "r"(mbq), "r"(512u) : "memory");

        // ---- partials: 2 cols x 2 batches x 32 k-pairs (f32x2) ----
        // Warp w reads kp [32w, 32w+32): each 16B broadcast feeds 4 FFMA2.
        const ulonglong2* hk =
            (const ulonglong2*)(dsm + HB_OFF + q * 4096 + w * 512);
        unsigned long long a0 = 0ull, a1 = 0ull, a2 = 0ull, a3 = 0ull;
#pragma unroll
        for (int j = 0; j < 32; j++) {
            ulonglong2 p = hk[j];             // .x = batch0 k-pair, .y = batch1
            unsigned long long ub = Usm[j * 256 + tid];
            asm("fma.rn.f32x2 %0, %1, %2, %0;" : "+l"(a0) : "l"(UA[j]), "l"(p.x));
            asm("fma.rn.f32x2 %0, %1, %2, %0;" : "+l"(a1) : "l"(UA[j]), "l"(p.y));
            asm("fma.rn.f32x2 %0, %1, %2, %0;" : "+l"(a2) : "l"(ub), "l"(p.x));
            asm("fma.rn.f32x2 %0, %1, %2, %0;" : "+l"(a3) : "l"(ub), "l"(p.y));
        }
        float s0, s1, s2, s3;
        {
            unsigned int l, h;
            asm("mov.b64 {%0, %1}, %2;" : "=r"(l), "=r"(h) : "l"(a0));
            s0 = __uint_as_float(l) + __uint_as_float(h);   // colA, b0
            asm("mov.b64 {%0, %1}, %2;" : "=r"(l), "=r"(h) : "l"(a1));
            s1 = __uint_as_float(l) + __uint_as_float(h);   // colA, b1
            asm("mov.b64 {%0, %1}, %2;" : "=r"(l), "=r"(h) : "l"(a2));
            s2 = __uint_as_float(l) + __uint_as_float(h);   // colB, b0
            asm("mov.b64 {%0, %1}, %2;" : "=r"(l), "=r"(h) : "l"(a3));
            s3 = __uint_as_float(l) + __uint_as_float(h);   // colB, b1
        }

        // red[q][comp][w][lane]: component-major, conflict-free.
        float* rq = redp + q * 1024;
        if (tid >= 128) {
            // Producers: protect red[q] reuse (epilogue read it at t-2;
            // arrive(3) at t-1 proves the read finished).
            if (t > 0)
                asm volatile("bar.sync 3, 256;" ::: "memory");
            rq[(0 * 8 + w) * 32 + lane] = s0;
            rq[(1 * 8 + w) * 32 + lane] = s1;
            rq[(2 * 8 + w) * 32 + lane] = s2;
            rq[(3 * 8 + w) * 32 + lane] = s3;
            // Release the epilogue; race ahead to the next wait.
            asm volatile("bar.arrive 2, 256;" ::: "memory");
        } else {
            rq[(0 * 8 + w) * 32 + lane] = s0;
            rq[(1 * 8 + w) * 32 + lane] = s1;
            rq[(2 * 8 + w) * 32 + lane] = s2;
            rq[(3 * 8 + w) * 32 + lane] = s3;
            // Wait for producers' red writes.
            asm volatile("bar.sync 2, 256;" ::: "memory");

            const float* rr = rq + ecomp * 256 + elane;
            float v = xw + (((rr[0 * 32] + rr[1 * 32]) +
                             (rr[2 * 32] + rr[3 * 32])) +
                            ((rr[4 * 32] + rr[5 * 32]) +
                             (rr[6 * 32] + rr[7 * 32])));
            v = fast_tanh(v);
            // Signal red[q] reads done (consumed by producers at t+1).
            asm volatile("bar.arrive 3, 256;" ::: "memory");

            // Write outgoing block into stage[q^1] (block-local layout).
            *(float*)(dsm + STG_OFF + (q ^ 1) * 512 +
                      (ec >> 1) * 16 + eb * 8 + (ec & 1) * 4) = v;

            hidden[gaddr] = v;               // overwrite xw[t] in place
            if (t == Ssz - 1)
                hlast[(size_t)(b0 + eb) * Hsz + egc] = v;
            else
                gaddr += Hsz;

            // Epilogue-only barrier: stage fully written before bulk reads.
            asm volatile("bar.sync 1, 128;" ::: "memory");

            // Push stage to ALL 8 ranks' hbuf[q^1] (self included),
            // complete_tx on the receiver's warp barrier mb[rank].
            if (tid < 8) {
                asm volatile("fence.proxy.async.shared::cta;" ::: "memory");
                const unsigned int src = stg_base + (unsigned int)(q ^ 1) * 512u;
                const unsigned int pr  = (rank + (unsigned int)tid) & 7u;
                const unsigned int dst_l =
                    hb_base + (unsigned int)(q ^ 1) * 4096u + rank * 512u;
                const unsigned int mb_tgt =
                    mb_base + rank * 16u + (unsigned int)(q ^ 1) * 8u;
                unsigned int dst, rmb;
                asm("mapa.shared::cluster.u32 %0, %1, %2;"
                    : "=r"(dst) : "r"(dst_l), "r"(pr));
                asm("mapa.shared::cluster.u32 %0, %1, %2;"
                    : "=r"(rmb) : "r"(mb_tgt), "r"(pr));
                asm volatile(
                    "cp.async.bulk.shared::cluster.shared::cta.mbarrier::complete_tx::bytes "
                    "[%0], [%1], %2, [%3];"
                    :: "r"(dst), "r"(src), "r"(512u), "r"(rmb) : "memory");
            }
        }
    }

    // Drain the final inbound phase, then cluster-sync before exit.
    mbar_wait(my_mb, ph0);
    asm volatile("barrier.cluster.arrive.aligned;" ::: "memory");
    asm volatile("barrier.cluster.wait.aligned;" ::: "memory");
}

extern "C" void kernel_launch(void* const* d_in, const int* in_sizes, int n_in,
                              void* d_out, int out_size) {
    const float* x  = (const float*)d_in[0];   // [64,2048,512]
    const float* Wi = (const float*)d_in[1];   // [512,512]
    const float* Ui = (const float*)d_in[2];   // [512,512]
    const float* bi = (const float*)d_in[3];   // [512]

    float* hidden = (float*)d_out;                        // [B,S,H]
    float* hlast  = hidden + (size_t)Bsz * Ssz * Hsz;     // [B,H]

    dim3 g1(Hsz / 128, (Bsz * Ssz) / 128);   // (4, 1024)
    sgemm_xw<<<g1, 256>>>(x, Wi, bi, hidden);

    // Phase 2: 32 clusters x 8 CTAs, 2 CTAs/SM, ~81 KB dyn smem each.
    cudaFuncSetAttribute(rnn_scan,
                         cudaFuncAttributeMaxDynamicSharedMemorySize,
                         SMEM_TOTAL);
    rnn_scan<<<256, 256, SMEM_TOTAL>>>(Ui, hidden, hlast);
}